// round 7
// baseline (speedup 1.0000x reference)
#include <cuda_runtime.h>

#define SEQ   4096
#define CIN   7
#define NUMK  74
#define KH    8
#define KW    3
#define D     1536
#define HALFD 768
#define TLEN  (SEQ * KW)   // 12288
#define SPER  8            // s-rows per block
#define NH    (3 * SPER)   // 24 conv h-values per block
#define NT    192          // threads per block

// ---------------- precomputed tables (device globals; no allocation) ----------------
// A[hi][i] = sincos(64*hi*div_i),  B[lo][i] = sincos(lo*div_i),  G[i] = sincos(div_i)
__device__ float g_A[64][HALFD][2];
__device__ float g_B[64][HALFD][2];
__device__ float g_G[HALFD][2];
// T2[a*7+b][f] = g(a)[f] + g(b)[f]   (temporal pair sums; indices are 0..6)
__device__ float g_T2[49][D];

// one table entry per thread: idx < 64*768 -> A/B/G entry (r,i); else T2 entry (p,i)
__global__ void init_tables_kernel()
{
    int idx = blockIdx.x * blockDim.x + threadIdx.x;
    const float cexp = (float)(-9.210340371976184 / 1536.0); // -ln(10000)/d

    if (idx < 64 * HALFD) {
        int i = idx % HALFD;
        int r = idx / HALFD;
        float div = expf((2.0f * (float)i) * cexp);
        float sh, ch, sl, cl;
        sincosf((float)(64 * r) * div, &sh, &ch);
        g_A[r][i][0] = sh; g_A[r][i][1] = ch;
        sincosf((float)r * div, &sl, &cl);
        g_B[r][i][0] = sl; g_B[r][i][1] = cl;
        if (r == 1) { g_G[i][0] = sl; g_G[i][1] = cl; }
    } else {
        int e = idx - 64 * HALFD;
        if (e < 49 * HALFD) {
            int i = e % HALFD;
            int p = e / HALFD;
            int a = p / 7, b = p % 7;
            float div = expf((2.0f * (float)i) * cexp);
            float sa, ca, sb, cb;
            sincosf((float)a * div, &sa, &ca);
            sincosf((float)b * div, &sb, &cb);
            g_T2[p][2 * i]     = sa + sb;
            g_T2[p][2 * i + 1] = ca + cb;
        }
    }
}

// dynamic smem layout (floats):
//   convS [NH][512]      : 12288 @ 0
//   wcsS  [KH][76]       : 608   @ 12288
//   sxS   [CIN][32]      : 224   @ 12896
//   t2iS  [SPER][2] int  : 16    @ 13120
#define SM_CONV   0
#define SM_WCS    12288
#define SM_SX     (SM_WCS + 608)
#define SM_T2I    (SM_SX + 224)
#define SMEM_BYTES ((SM_T2I + SPER * 2) * 4 + 64)

// ---------------- main kernel: 192 threads; thread owns TWO columns for 8 rows ----------------
__global__ __launch_bounds__(NT, 4) void embed_kernel(
    const float* __restrict__ x,       // (4096, 7)
    const float* __restrict__ kern,    // (74, 8, 3)
    const int*   __restrict__ xm,      // (4096, 4)
    float*       __restrict__ out)     // (4096, 1536)
{
    extern __shared__ float smem[];
    float* __restrict__ convS = smem + SM_CONV;   // [NH][512], h-major
    float* __restrict__ wcsS  = smem + SM_WCS;    // [k][76]
    float* __restrict__ sxS   = smem + SM_SX;     // [c][32], 31 used
    int*   __restrict__ t2iS  = (int*)(smem + SM_T2I);

    const int s0  = blockIdx.x * SPER;   // aligned: hi = s>>6 constant; lo0+7 <= 63
    const int tid = threadIdx.x;

    // ---- stage weights: wc[o][k] = kern[o*24 + k*3 + 1]
    for (int e = tid; e < NUMK * KH; e += NT) {
        int o = e / KH, k = e - o * KH;
        wcsS[k * 76 + o] = kern[o * (KH * KW) + k * KW + 1];
    }
    // ---- stage x window: i in [0,31), t = 3*s0 - 4 + i   (CIN*31 = 217 > NT -> loop)
    for (int e = tid; e < CIN * 31; e += NT) {
        int c = e / 31, i = e - c * 31;
        int t = 3 * s0 - 4 + i;
        float v = 0.0f;
        if (t >= 0 && t < TLEN) {
            int row = t / 3 + t % 3;
            if (row > SEQ - 1) row = SEQ - 1;
            v = x[row * CIN + c];
        }
        sxS[c * 32 + i] = v;
    }
    // ---- stage temporal table indices
    if (tid < SPER) {
        int s = s0 + tid;
        int i0 = xm[s * 4 + 0], i1 = xm[s * 4 + 1],
            i2 = xm[s * 4 + 2], i3 = xm[s * 4 + 3];
        t2iS[2 * tid]     = i3 * 7 + i2;
        t2iS[2 * tid + 1] = i1 * 7 + i0;
    }
    __syncthreads();

    // =========== Phase 1: conv into smem, g = tid, tid+192, (tid+384 if tid<128) ==========
    for (int g = tid; g < 512; g += NT) {
        int c, o;
        if (g == 511) { c = 0; o = NUMK - 1; }
        else          { c = g / 73; o = g - c * 73; }

        float w[8];
#pragma unroll
        for (int k = 0; k < 8; k++) w[k] = wcsS[k * 76 + o];

        const float* __restrict__ sxc = sxS + c * 32;
        float v[8];
#pragma unroll
        for (int k = 0; k < 8; k++) v[k] = sxc[k];

#pragma unroll
        for (int h = 0; h < NH; h++) {
            float a0 = v[(h + 0) & 7] * w[0] + v[(h + 1) & 7] * w[1]
                     + v[(h + 2) & 7] * w[2] + v[(h + 3) & 7] * w[3];
            float a1 = v[(h + 4) & 7] * w[4] + v[(h + 5) & 7] * w[5]
                     + v[(h + 6) & 7] * w[6] + v[(h + 7) & 7] * w[7];
            convS[h * 512 + g] = a0 + a1;
            if (h < NH - 1) v[h & 7] = sxc[h + 8];
        }
    }
    __syncthreads();

    // =========== Phase 2: two columns per thread, 8 rows, pe rotated in registers ==========
    // column indices cf0 = tid, cf1 = tid+192 of 0..383; f = (cf>>7)*512 + 4*(cf&127)
    const int cf0 = tid, cf1 = tid + NT;
    const int f0 = (cf0 >> 7) * 512 + 4 * (cf0 & 127);
    const int f1 = (cf1 >> 7) * 512 + 4 * (cf1 & 127);
    const int hi  = s0 >> 6;
    const int lo0 = s0 & 63;

    // seeds: pe(s0) = A(hi) (+) B(lo0)   [layout: s,c,s,c]
    const float4 av0 = *(const float4*)(&g_A[hi][0][0] + f0);
    const float4 bv0 = *(const float4*)(&g_B[lo0][0][0] + f0);
    const float4 av1 = *(const float4*)(&g_A[hi][0][0] + f1);
    const float4 bv1 = *(const float4*)(&g_B[lo0][0][0] + f1);
    const float4 gv0 = *(const float4*)(&g_G[0][0] + f0);
    const float4 gv1 = *(const float4*)(&g_G[0][0] + f1);

    float4 pe0, pe1;
    pe0.x = av0.x * bv0.y + av0.y * bv0.x;  pe0.y = av0.y * bv0.y - av0.x * bv0.x;
    pe0.z = av0.z * bv0.w + av0.w * bv0.z;  pe0.w = av0.w * bv0.w - av0.z * bv0.z;
    pe1.x = av1.x * bv1.y + av1.y * bv1.x;  pe1.y = av1.y * bv1.y - av1.x * bv1.x;
    pe1.z = av1.z * bv1.w + av1.w * bv1.z;  pe1.w = av1.w * bv1.w - av1.z * bv1.z;

    // depth-1 prefetch of row-0 T2 data for both columns (4 loads in flight)
    int ja = t2iS[0], jb = t2iS[1];
    float4 ta0 = *(const float4*)(g_T2[ja] + f0);
    float4 tb0 = *(const float4*)(g_T2[jb] + f0);
    float4 ta1 = *(const float4*)(g_T2[ja] + f1);
    float4 tb1 = *(const float4*)(g_T2[jb] + f1);

    float* __restrict__ outp0 = out + (size_t)s0 * D + f0;
    float* __restrict__ outp1 = out + (size_t)s0 * D + f1;
    const float* __restrict__ cvp0 = convS + (f0 >> 9) * 512 + (f0 & 511); // jj*512+g0
    const float* __restrict__ cvp1 = convS + (f1 >> 9) * 512 + (f1 & 511);

#pragma unroll
    for (int r = 0; r < SPER; r++) {
        const float4 A0 = ta0, B0 = tb0, A1 = ta1, B1 = tb1;
        if (r < SPER - 1) {
            const int na = t2iS[2 * (r + 1)], nb = t2iS[2 * (r + 1) + 1];
            ta0 = *(const float4*)(g_T2[na] + f0);
            tb0 = *(const float4*)(g_T2[nb] + f0);
            ta1 = *(const float4*)(g_T2[na] + f1);
            tb1 = *(const float4*)(g_T2[nb] + f1);
        }
        const float4 cv0 = *(const float4*)(cvp0 + r * 3 * 512);
        const float4 cv1 = *(const float4*)(cvp1 + r * 3 * 512);

        float4 r0, r1;
        r0.x = cv0.x + pe0.x + A0.x + B0.x;
        r0.y = cv0.y + pe0.y + A0.y + B0.y;
        r0.z = cv0.z + pe0.z + A0.z + B0.z;
        r0.w = cv0.w + pe0.w + A0.w + B0.w;
        r1.x = cv1.x + pe1.x + A1.x + B1.x;
        r1.y = cv1.y + pe1.y + A1.y + B1.y;
        r1.z = cv1.z + pe1.z + A1.z + B1.z;
        r1.w = cv1.w + pe1.w + A1.w + B1.w;
        *(float4*)outp0 = r0;
        *(float4*)outp1 = r1;

        // rotate pe by div_f for next row
        float4 n0, n1;
        n0.x = pe0.x * gv0.y + pe0.y * gv0.x;  n0.y = pe0.y * gv0.y - pe0.x * gv0.x;
        n0.z = pe0.z * gv0.w + pe0.w * gv0.z;  n0.w = pe0.w * gv0.w - pe0.z * gv0.z;
        n1.x = pe1.x * gv1.y + pe1.y * gv1.x;  n1.y = pe1.y * gv1.y - pe1.x * gv1.x;
        n1.z = pe1.z * gv1.w + pe1.w * gv1.z;  n1.w = pe1.w * gv1.w - pe1.z * gv1.z;
        pe0 = n0; pe1 = n1;

        outp0 += D;
        outp1 += D;
    }
}

// ---------------- launch ----------------
extern "C" void kernel_launch(void* const* d_in, const int* in_sizes, int n_in,
                              void* d_out, int out_size)
{
    const float* x     = nullptr;
    const float* kern  = nullptr;
    const int*   xmark = nullptr;
    for (int i = 0; i < n_in; i++) {
        if      (in_sizes[i] == SEQ * CIN)        x     = (const float*)d_in[i];
        else if (in_sizes[i] == NUMK * KH * KW)   kern  = (const float*)d_in[i];
        else if (in_sizes[i] == SEQ * 4)          xmark = (const int*)d_in[i];
    }

    cudaFuncSetAttribute(embed_kernel,
                         cudaFuncAttributeMaxDynamicSharedMemorySize, SMEM_BYTES);

    const int init_threads = (64 + 49) * HALFD;
    init_tables_kernel<<<(init_threads + 255) / 256, 256>>>();
    embed_kernel<<<SEQ / SPER, NT, SMEM_BYTES>>>(x, kern, xmark, (float*)d_out);
}

// round 8
// speedup vs baseline: 1.2598x; 1.2598x over previous
#include <cuda_runtime.h>

#define SEQ   4096
#define CIN   7
#define NUMK  74
#define KH    8
#define KW    3
#define D     1536
#define HALFD 768
#define TLEN  (SEQ * KW)   // 12288
#define SPER  8            // s-rows per block
#define NH    (3 * SPER)   // 24 conv h-values per block
#define NT    384          // threads per block

// dynamic smem layout (floats):
//   convS [NH][512]   : 12288 @ 0
//   wcsS  [KH][76]    : 608   @ 12288
//   sxS   [CIN][32]   : 224   @ 12896
//   mS    [SPER][8]   : 64    @ 13120   (temporal multiplicities, m[r][a], a<7)
#define SM_CONV   0
#define SM_WCS    12288
#define SM_SX     (SM_WCS + 608)
#define SM_M      (SM_SX + 224)
#define SMEM_BYTES ((SM_M + SPER * 8) * 4)

// ---------------- single kernel: conv to smem, then tables-by-rotation ----------------
__global__ __launch_bounds__(NT, 3) void embed_kernel(
    const float* __restrict__ x,       // (4096, 7)
    const float* __restrict__ kern,    // (74, 8, 3)
    const int*   __restrict__ xm,      // (4096, 4)
    float*       __restrict__ out)     // (4096, 1536)
{
    extern __shared__ float smem[];
    float* __restrict__ convS = smem + SM_CONV;   // [NH][512], h-major
    float* __restrict__ wcsS  = smem + SM_WCS;    // [k][76]
    float* __restrict__ sxS   = smem + SM_SX;     // [c][32], 31 used
    float* __restrict__ mS    = smem + SM_M;      // [SPER][8]

    const int s0  = blockIdx.x * SPER;
    const int tid = threadIdx.x;

    // ---- stage weights: wc[o][k] = kern[o*24 + k*3 + 1]
    for (int e = tid; e < NUMK * KH; e += NT) {
        int o = e / KH, k = e - o * KH;
        wcsS[k * 76 + o] = kern[o * (KH * KW) + k * KW + 1];
    }
    // ---- stage x window: i in [0,31), t = 3*s0 - 4 + i
    if (tid < CIN * 31) {
        int c = tid / 31, i = tid - c * 31;
        int t = 3 * s0 - 4 + i;
        float v = 0.0f;
        if (t >= 0 && t < TLEN) {
            int row = t / 3 + t % 3;
            if (row > SEQ - 1) row = SEQ - 1;
            v = x[row * CIN + c];
        }
        sxS[c * 32 + i] = v;
    }
    // ---- stage temporal multiplicities: m[r][a] = #{k : xm[s0+r][k] == a}
    if (tid >= 320 && tid < 320 + SPER * 7) {
        int e = tid - 320;
        int r = e / 7, a = e - r * 7;
        const int* xr = xm + (s0 + r) * 4;
        int m = (xr[0] == a) + (xr[1] == a) + (xr[2] == a) + (xr[3] == a);
        mS[r * 8 + a] = (float)m;
    }
    __syncthreads();

    // =========== Phase 1: conv into smem; thread owns g = tid (+384 for tid<128) ==========
    for (int g = tid; g < 512; g += NT) {
        int c, o;
        if (g == 511) { c = 0; o = NUMK - 1; }
        else          { c = g / 73; o = g - c * 73; }

        float w[8];
#pragma unroll
        for (int k = 0; k < 8; k++) w[k] = wcsS[k * 76 + o];

        const float* __restrict__ sxc = sxS + c * 32;
        float v[8];
#pragma unroll
        for (int k = 0; k < 8; k++) v[k] = sxc[k];

#pragma unroll
        for (int h = 0; h < NH; h++) {
            float a0 = v[(h + 0) & 7] * w[0] + v[(h + 1) & 7] * w[1]
                     + v[(h + 2) & 7] * w[2] + v[(h + 3) & 7] * w[3];
            float a1 = v[(h + 4) & 7] * w[4] + v[(h + 5) & 7] * w[5]
                     + v[(h + 6) & 7] * w[6] + v[(h + 7) & 7] * w[7];
            convS[h * 512 + g] = a0 + a1;
            if (h < NH - 1) v[h & 7] = sxc[h + 8];
        }
    }
    __syncthreads();

    // =========== Phase 2: one float4 column per thread; pe + temporal by rotation ==========
    const int lane = tid & 127;          // 0..127
    const int jj   = tid >> 7;           // 0..2
    const int g0   = 4 * lane;
    const int f    = jj * 512 + g0;      // even; covers dims f..f+3 = pairs (i0, i0+1)

    const float cexp = (float)(-9.210340371976184 / 1536.0); // -ln(10000)/d
    const float div0 = expf((float)(f)     * cexp);          // div for i0 = f/2
    const float div1 = expf((float)(f + 2) * cexp);          // div for i0+1

    // pe(s0) seed
    float ps0, pc0, ps1, pc1;
    sincosf((float)s0 * div0, &ps0, &pc0);
    sincosf((float)s0 * div1, &ps1, &pc1);
    // per-row rotation step
    float gs0, gc0, gs1, gc1;
    sincosf(div0, &gs0, &gc0);
    sincosf(div1, &gs1, &gc1);

    // temporal basis T[a] = sincos(a*div), a = 1..6, built by rotation
    float Ts0[7], Tc0[7], Ts1[7], Tc1[7];
    Ts0[1] = gs0; Tc0[1] = gc0; Ts1[1] = gs1; Tc1[1] = gc1;
#pragma unroll
    for (int a = 2; a <= 6; a++) {
        Ts0[a] = Ts0[a-1] * gc0 + Tc0[a-1] * gs0;
        Tc0[a] = Tc0[a-1] * gc0 - Ts0[a-1] * gs0;
        Ts1[a] = Ts1[a-1] * gc1 + Tc1[a-1] * gs1;
        Tc1[a] = Tc1[a-1] * gc1 - Ts1[a-1] * gs1;
    }

    float* __restrict__ outp = out + (size_t)s0 * D + f;
    const float* __restrict__ cvp = convS + jj * 512 + g0;   // +1536 per row

#pragma unroll
    for (int r = 0; r < SPER; r++) {
        const float4 mA = *(const float4*)(mS + r * 8);      // m[0..3]
        const float4 mB = *(const float4*)(mS + r * 8 + 4);  // m[4..6], pad
        const float4 cv = *(const float4*)(cvp + r * 3 * 512);

        // temporal = sum_a m[a] * T[a]   (T[0] = (0,1) folds to +m0 on cos lanes)
        float t_s0 = mA.y * Ts0[1] + mA.z * Ts0[2] + mA.w * Ts0[3]
                   + mB.x * Ts0[4] + mB.y * Ts0[5] + mB.z * Ts0[6];
        float t_c0 = mA.x + mA.y * Tc0[1] + mA.z * Tc0[2] + mA.w * Tc0[3]
                   + mB.x * Tc0[4] + mB.y * Tc0[5] + mB.z * Tc0[6];
        float t_s1 = mA.y * Ts1[1] + mA.z * Ts1[2] + mA.w * Ts1[3]
                   + mB.x * Ts1[4] + mB.y * Ts1[5] + mB.z * Ts1[6];
        float t_c1 = mA.x + mA.y * Tc1[1] + mA.z * Tc1[2] + mA.w * Tc1[3]
                   + mB.x * Tc1[4] + mB.y * Tc1[5] + mB.z * Tc1[6];

        float4 res;
        res.x = cv.x + ps0 + t_s0;
        res.y = cv.y + pc0 + t_c0;
        res.z = cv.z + ps1 + t_s1;
        res.w = cv.w + pc1 + t_c1;
        *(float4*)outp = res;

        // rotate pe by div for next row
        float ns0 = ps0 * gc0 + pc0 * gs0;
        float nc0 = pc0 * gc0 - ps0 * gs0;
        float ns1 = ps1 * gc1 + pc1 * gs1;
        float nc1 = pc1 * gc1 - ps1 * gs1;
        ps0 = ns0; pc0 = nc0; ps1 = ns1; pc1 = nc1;

        outp += D;
    }
}

// ---------------- launch ----------------
extern "C" void kernel_launch(void* const* d_in, const int* in_sizes, int n_in,
                              void* d_out, int out_size)
{
    const float* x     = nullptr;
    const float* kern  = nullptr;
    const int*   xmark = nullptr;
    for (int i = 0; i < n_in; i++) {
        if      (in_sizes[i] == SEQ * CIN)        x     = (const float*)d_in[i];
        else if (in_sizes[i] == NUMK * KH * KW)   kern  = (const float*)d_in[i];
        else if (in_sizes[i] == SEQ * 4)          xmark = (const int*)d_in[i];
    }

    cudaFuncSetAttribute(embed_kernel,
                         cudaFuncAttributeMaxDynamicSharedMemorySize, SMEM_BYTES);

    embed_kernel<<<SEQ / SPER, NT, SMEM_BYTES>>>(x, kern, xmark, (float*)d_out);
}

// round 9
// speedup vs baseline: 1.2879x; 1.0223x over previous
#include <cuda_runtime.h>

#define SEQ   4096
#define CIN   7
#define NUMK  74
#define KH    8
#define KW    3
#define D     1536
#define HALFD 768
#define TLEN  (SEQ * KW)   // 12288
#define SPER  8            // s-rows per block
#define NH    (3 * SPER)   // 24 conv h-values per block
#define NT    384          // threads per block

// ---- packed f32x2 helpers (sm_100a) ----
typedef unsigned long long u64;
#define F2PACK(d, lo, hi)   asm("mov.b64 %0, {%1, %2};"      : "=l"(d) : "f"(lo), "f"(hi))
#define F2UNPACK(lo, hi, s) asm("mov.b64 {%0, %1}, %2;"      : "=f"(lo), "=f"(hi) : "l"(s))
#define F2MUL(d, a, b)      asm("mul.rn.f32x2 %0, %1, %2;"   : "=l"(d) : "l"(a), "l"(b))
#define F2FMA(d, a, b, c)   asm("fma.rn.f32x2 %0, %1, %2, %3;" : "=l"(d) : "l"(a), "l"(b), "l"(c))

// dynamic smem layout (floats):
//   convS [NH][512]   : 12288 @ 0
//   wcsS  [KH][76]    : 608   @ 12288
//   sxS   [CIN][32]   : 224   @ 12896
//   mS    [SPER][8]   : 64    @ 13120   (temporal multiplicities, m[r][a], a<7)
#define SM_CONV   0
#define SM_WCS    12288
#define SM_SX     (SM_WCS + 608)
#define SM_M      (SM_SX + 224)
#define SMEM_BYTES ((SM_M + SPER * 8) * 4)

// packed-pair conv for one column: h in [hr, hr+2*nsteps), results to convS[h][g]
__device__ __forceinline__ void conv_col(
    const float* __restrict__ sxc,    // channel window, 31 valid
    const float* __restrict__ wcsS,   // [k][76]
    int o, int g, int hr, int nsteps,
    float* __restrict__ convS)
{
    // packed weights (w_k, w_k)
    u64 wp[8];
#pragma unroll
    for (int k = 0; k < 8; k++) {
        float w = wcsS[k * 76 + o];
        F2PACK(wp[k], w, w);
    }
    // ring of 8 packs: P[(hr+j)&7] = (sxc[hr+j], sxc[hr+j+1]), j = 0..7  (hr % 8 == 0)
    u64 P[8];
    float prev = sxc[hr];
#pragma unroll
    for (int j = 0; j < 8; j++) {
        float nx = sxc[hr + j + 1];
        F2PACK(P[j], prev, nx);
        prev = nx;
    }
    float last = prev;                 // sxc[hr+8]

#pragma unroll
    for (int t = 0; t < nsteps; t++) {
        const int h = hr + 2 * t;
        u64 acc;
        F2MUL(acc, wp[0], P[(2 * t) & 7]);
#pragma unroll
        for (int k = 1; k < 8; k++)
            F2FMA(acc, wp[k], P[(2 * t + k) & 7], acc);
        float lo, hi;
        F2UNPACK(lo, hi, acc);
        convS[h * 512 + g]       = lo;
        convS[(h + 1) * 512 + g] = hi;
        if (t < nsteps - 1) {
            float n1 = sxc[hr + 2 * t + 9];
            float n2 = sxc[hr + 2 * t + 10];
            F2PACK(P[(2 * t) & 7],     last, n1);
            F2PACK(P[(2 * t + 1) & 7], n1,   n2);
            last = n2;
        }
    }
}

// ---------------- single kernel: conv to smem, then tables-by-rotation ----------------
__global__ __launch_bounds__(NT, 3) void embed_kernel(
    const float* __restrict__ x,       // (4096, 7)
    const float* __restrict__ kern,    // (74, 8, 3)
    const int*   __restrict__ xm,      // (4096, 4)
    float*       __restrict__ out)     // (4096, 1536)
{
    extern __shared__ float smem[];
    float* __restrict__ convS = smem + SM_CONV;   // [NH][512], h-major
    float* __restrict__ wcsS  = smem + SM_WCS;    // [k][76]
    float* __restrict__ sxS   = smem + SM_SX;     // [c][32], 31 used
    float* __restrict__ mS    = smem + SM_M;      // [SPER][8]

    const int s0  = blockIdx.x * SPER;
    const int tid = threadIdx.x;

    // ---- stage weights: wc[o][k] = kern[o*24 + k*3 + 1]
    for (int e = tid; e < NUMK * KH; e += NT) {
        int o = e / KH, k = e - o * KH;
        wcsS[k * 76 + o] = kern[o * (KH * KW) + k * KW + 1];
    }
    // ---- stage x window: i in [0,31), t = 3*s0 - 4 + i
    if (tid < CIN * 31) {
        int c = tid / 31, i = tid - c * 31;
        int t = 3 * s0 - 4 + i;
        float v = 0.0f;
        if (t >= 0 && t < TLEN) {
            int row = t / 3 + t % 3;
            if (row > SEQ - 1) row = SEQ - 1;
            v = x[row * CIN + c];
        }
        sxS[c * 32 + i] = v;
    }
    // ---- stage temporal multiplicities: m[r][a] = #{k : xm[s0+r][k] == a}
    if (tid >= 320 && tid < 320 + SPER * 7) {
        int e = tid - 320;
        int r = e / 7, a = e - r * 7;
        const int* xr = xm + (s0 + r) * 4;
        int m = (xr[0] == a) + (xr[1] == a) + (xr[2] == a) + (xr[3] == a);
        mS[r * 8 + a] = (float)m;
    }
    __syncthreads();

    // =========== Phase 1 (balanced): full column g = tid; plus an 8-h chunk of cols 384..511 ==========
    {
        const int g = tid;                       // 0..383 -> c <= 5, never 511
        const int c = g / 73, o = g - c * 73;
        conv_col(sxS + c * 32, wcsS, o, g, 0, NH / 2, convS);
    }
    {
        const int g  = 384 + (tid & 127);        // 384..511
        const int hr = (tid >> 7) * 8;           // 0, 8, 16
        int c, o;
        if (g == 511) { c = 0; o = NUMK - 1; }
        else          { c = g / 73; o = g - c * 73; }
        conv_col(sxS + c * 32, wcsS, o, g, hr, 4, convS);
    }
    __syncthreads();

    // =========== Phase 2: one float4 column per thread; pe + temporal by rotation ==========
    const int lane = tid & 127;          // 0..127
    const int jj   = tid >> 7;           // 0..2
    const int g0   = 4 * lane;
    const int f    = jj * 512 + g0;      // even; covers dims f..f+3 = pairs (i0, i0+1)

    const float cexp = (float)(-9.210340371976184 / 1536.0); // -ln(10000)/d
    const float div0 = expf((float)(f)     * cexp);          // div for i0 = f/2
    const float div1 = expf((float)(f + 2) * cexp);          // div for i0+1

    // pe(s0) seed
    float ps0, pc0, ps1, pc1;
    sincosf((float)s0 * div0, &ps0, &pc0);
    sincosf((float)s0 * div1, &ps1, &pc1);
    // per-row rotation step
    float gs0, gc0, gs1, gc1;
    sincosf(div0, &gs0, &gc0);
    sincosf(div1, &gs1, &gc1);

    // temporal basis T[a] = sincos(a*div), a = 1..6, built by rotation
    float Ts0[7], Tc0[7], Ts1[7], Tc1[7];
    Ts0[1] = gs0; Tc0[1] = gc0; Ts1[1] = gs1; Tc1[1] = gc1;
#pragma unroll
    for (int a = 2; a <= 6; a++) {
        Ts0[a] = Ts0[a-1] * gc0 + Tc0[a-1] * gs0;
        Tc0[a] = Tc0[a-1] * gc0 - Ts0[a-1] * gs0;
        Ts1[a] = Ts1[a-1] * gc1 + Tc1[a-1] * gs1;
        Tc1[a] = Tc1[a-1] * gc1 - Ts1[a-1] * gs1;
    }

    float* __restrict__ outp = out + (size_t)s0 * D + f;
    const float* __restrict__ cvp = convS + jj * 512 + g0;   // +1536 per row

#pragma unroll
    for (int r = 0; r < SPER; r++) {
        const float4 mA = *(const float4*)(mS + r * 8);      // m[0..3]
        const float4 mB = *(const float4*)(mS + r * 8 + 4);  // m[4..6], pad
        const float4 cv = *(const float4*)(cvp + r * 3 * 512);

        // temporal = sum_a m[a] * T[a]   (T[0] = (0,1) folds to +m0 on cos lanes)
        float t_s0 = mA.y * Ts0[1] + mA.z * Ts0[2] + mA.w * Ts0[3]
                   + mB.x * Ts0[4] + mB.y * Ts0[5] + mB.z * Ts0[6];
        float t_c0 = mA.x + mA.y * Tc0[1] + mA.z * Tc0[2] + mA.w * Tc0[3]
                   + mB.x * Tc0[4] + mB.y * Tc0[5] + mB.z * Tc0[6];
        float t_s1 = mA.y * Ts1[1] + mA.z * Ts1[2] + mA.w * Ts1[3]
                   + mB.x * Ts1[4] + mB.y * Ts1[5] + mB.z * Ts1[6];
        float t_c1 = mA.x + mA.y * Tc1[1] + mA.z * Tc1[2] + mA.w * Tc1[3]
                   + mB.x * Tc1[4] + mB.y * Tc1[5] + mB.z * Tc1[6];

        float4 res;
        res.x = cv.x + ps0 + t_s0;
        res.y = cv.y + pc0 + t_c0;
        res.z = cv.z + ps1 + t_s1;
        res.w = cv.w + pc1 + t_c1;
        *(float4*)outp = res;

        // rotate pe by div for next row
        float ns0 = ps0 * gc0 + pc0 * gs0;
        float nc0 = pc0 * gc0 - ps0 * gs0;
        float ns1 = ps1 * gc1 + pc1 * gs1;
        float nc1 = pc1 * gc1 - ps1 * gs1;
        ps0 = ns0; pc0 = nc0; ps1 = ns1; pc1 = nc1;

        outp += D;
    }
}

// ---------------- launch ----------------
extern "C" void kernel_launch(void* const* d_in, const int* in_sizes, int n_in,
                              void* d_out, int out_size)
{
    const float* x     = nullptr;
    const float* kern  = nullptr;
    const int*   xmark = nullptr;
    for (int i = 0; i < n_in; i++) {
        if      (in_sizes[i] == SEQ * CIN)        x     = (const float*)d_in[i];
        else if (in_sizes[i] == NUMK * KH * KW)   kern  = (const float*)d_in[i];
        else if (in_sizes[i] == SEQ * 4)          xmark = (const int*)d_in[i];
    }

    cudaFuncSetAttribute(embed_kernel,
                         cudaFuncAttributeMaxDynamicSharedMemorySize, SMEM_BYTES);

    embed_kernel<<<SEQ / SPER, NT, SMEM_BYTES>>>(x, kern, xmark, (float*)d_out);
}

// round 10
// speedup vs baseline: 1.3608x; 1.0566x over previous
#include <cuda_runtime.h>

#define SEQ   4096
#define CIN   7
#define NUMK  74
#define KH    8
#define KW    3
#define D     1536
#define HALFD 768
#define TLEN  (SEQ * KW)   // 12288
#define SPER  8            // s-rows per block
#define NH    (3 * SPER)   // 24 conv h-values per block
#define NT    384          // threads per block

// ---- packed f32x2 helpers (sm_100a) ----
typedef unsigned long long u64;
#define F2PACK(d, lo, hi)   asm("mov.b64 %0, {%1, %2};"      : "=l"(d) : "f"(lo), "f"(hi))
#define F2UNPACK(lo, hi, s) asm("mov.b64 {%0, %1}, %2;"      : "=f"(lo), "=f"(hi) : "l"(s))
#define F2MUL(d, a, b)      asm("mul.rn.f32x2 %0, %1, %2;"   : "=l"(d) : "l"(a), "l"(b))
#define F2FMA(d, a, b, c)   asm("fma.rn.f32x2 %0, %1, %2, %3;" : "=l"(d) : "l"(a), "l"(b), "l"(c))

// dynamic smem layout (floats):
//   convS [NH][512]   : 12288 @ 0
//   wcsS  [KH][76]    : 608   @ 12288
//   sxS   [CIN][32]   : 224   @ 12896
//   mS    [SPER][16]  : 128   @ 13120   (duplicated multiplicity pairs, 8B-aligned)
#define SM_CONV   0
#define SM_WCS    12288
#define SM_SX     (SM_WCS + 608)
#define SM_M      (SM_SX + 224)
#define SMEM_BYTES ((SM_M + SPER * 16) * 4)

// packed-pair conv for one column: h in [hr, hr+2*nsteps), results to convS[h][g]
__device__ __forceinline__ void conv_col(
    const float* __restrict__ sxc,    // channel window, 31 valid
    const float* __restrict__ wcsS,   // [k][76]
    int o, int g, int hr, int nsteps,
    float* __restrict__ convS)
{
    u64 wp[8];
#pragma unroll
    for (int k = 0; k < 8; k++) {
        float w = wcsS[k * 76 + o];
        F2PACK(wp[k], w, w);
    }
    u64 P[8];
    float prev = sxc[hr];
#pragma unroll
    for (int j = 0; j < 8; j++) {
        float nx = sxc[hr + j + 1];
        F2PACK(P[j], prev, nx);
        prev = nx;
    }
    float last = prev;                 // sxc[hr+8]

#pragma unroll
    for (int t = 0; t < nsteps; t++) {
        const int h = hr + 2 * t;
        u64 acc;
        F2MUL(acc, wp[0], P[(2 * t) & 7]);
#pragma unroll
        for (int k = 1; k < 8; k++)
            F2FMA(acc, wp[k], P[(2 * t + k) & 7], acc);
        float lo, hi;
        F2UNPACK(lo, hi, acc);
        convS[h * 512 + g]       = lo;
        convS[(h + 1) * 512 + g] = hi;
        if (t < nsteps - 1) {
            float n1 = sxc[hr + 2 * t + 9];
            float n2 = sxc[hr + 2 * t + 10];
            F2PACK(P[(2 * t) & 7],     last, n1);
            F2PACK(P[(2 * t + 1) & 7], n1,   n2);
            last = n2;
        }
    }
}

// ---------------- single kernel: conv to smem, then tables-by-rotation ----------------
__global__ __launch_bounds__(NT, 3) void embed_kernel(
    const float* __restrict__ x,       // (4096, 7)
    const float* __restrict__ kern,    // (74, 8, 3)
    const int*   __restrict__ xm,      // (4096, 4)
    float*       __restrict__ out)     // (4096, 1536)
{
    extern __shared__ float smem[];
    float* __restrict__ convS = smem + SM_CONV;   // [NH][512], h-major
    float* __restrict__ wcsS  = smem + SM_WCS;    // [k][76]
    float* __restrict__ sxS   = smem + SM_SX;     // [c][32], 31 used
    float* __restrict__ mS    = smem + SM_M;      // [SPER][16] duplicated pairs

    const int s0  = blockIdx.x * SPER;
    const int tid = threadIdx.x;

    // ---- stage weights: wc[o][k] = kern[o*24 + k*3 + 1]
    for (int e = tid; e < NUMK * KH; e += NT) {
        int o = e / KH, k = e - o * KH;
        wcsS[k * 76 + o] = kern[o * (KH * KW) + k * KW + 1];
    }
    // ---- stage x window: i in [0,31), t = 3*s0 - 4 + i
    if (tid < CIN * 31) {
        int c = tid / 31, i = tid - c * 31;
        int t = 3 * s0 - 4 + i;
        float v = 0.0f;
        if (t >= 0 && t < TLEN) {
            int row = t / 3 + t % 3;
            if (row > SEQ - 1) row = SEQ - 1;
            v = x[row * CIN + c];
        }
        sxS[c * 32 + i] = v;
    }
    // ---- stage duplicated temporal multiplicity pairs:
    //      mS[r][2a, 2a+1] = (a==0 ? 0 : m, m) where m = #{k : xm[s0+r][k]==a}
    if (tid >= 320 && tid < 320 + SPER * 7) {
        int e = tid - 320;
        int r = e / 7, a = e - r * 7;
        const int* xr = xm + (s0 + r) * 4;
        float m = (float)((xr[0] == a) + (xr[1] == a) + (xr[2] == a) + (xr[3] == a));
        mS[r * 16 + 2 * a]     = (a == 0) ? 0.0f : m;
        mS[r * 16 + 2 * a + 1] = m;
    }
    __syncthreads();

    // =========== Phase 1 (balanced): full column g = tid; plus an 8-h chunk of cols 384..511 ==========
    {
        const int g = tid;                       // 0..383 -> c <= 5, never 511
        const int c = g / 73, o = g - c * 73;
        conv_col(sxS + c * 32, wcsS, o, g, 0, NH / 2, convS);
    }
    {
        const int g  = 384 + (tid & 127);        // 384..511
        const int hr = (tid >> 7) * 8;           // 0, 8, 16
        int c, o;
        if (g == 511) { c = 0; o = NUMK - 1; }
        else          { c = g / 73; o = g - c * 73; }
        conv_col(sxS + c * 32, wcsS, o, g, hr, 4, convS);
    }
    __syncthreads();

    // =========== Phase 2: one float4 column per thread; pe + temporal by rotation ==========
    const int lane = tid & 127;          // 0..127
    const int jj   = tid >> 7;           // 0..2
    const int g0   = 4 * lane;
    const int f    = jj * 512 + g0;      // even; covers dims f..f+3 = pairs (i0, i0+1)

    const float cexp = (float)(-9.210340371976184 / 1536.0); // -ln(10000)/d
    const float div0 = expf((float)(f) * cexp);              // div for i0 = f/2
    const float div1 = div0 * 0.988078993f;                  // * 10000^(-2/1536)

    // pe(s0) seed
    float ps0, pc0, ps1, pc1;
    sincosf((float)s0 * div0, &ps0, &pc0);
    sincosf((float)s0 * div1, &ps1, &pc1);
    // per-row rotation step
    float gs0, gc0, gs1, gc1;
    sincosf(div0, &gs0, &gc0);
    sincosf(div1, &gs1, &gc1);

    // packed temporal basis Tp[a] = (sin(a*div), cos(a*div)), a = 0..6
    u64 Tp0[7], Tp1[7];
    F2PACK(Tp0[0], 0.0f, 1.0f);
    F2PACK(Tp1[0], 0.0f, 1.0f);
    F2PACK(Tp0[1], gs0, gc0);
    F2PACK(Tp1[1], gs1, gc1);
    {
        float ts0 = gs0, tc0 = gc0, ts1 = gs1, tc1 = gc1;
#pragma unroll
        for (int a = 2; a <= 6; a++) {
            float ns0 = ts0 * gc0 + tc0 * gs0;
            float nc0 = tc0 * gc0 - ts0 * gs0;
            float ns1 = ts1 * gc1 + tc1 * gs1;
            float nc1 = tc1 * gc1 - ts1 * gs1;
            ts0 = ns0; tc0 = nc0; ts1 = ns1; tc1 = nc1;
            F2PACK(Tp0[a], ts0, tc0);
            F2PACK(Tp1[a], ts1, tc1);
        }
    }

    float* __restrict__ outp = out + (size_t)s0 * D + f;
    const float* __restrict__ cvp = convS + jj * 512 + g0;   // +1536 per row

#pragma unroll
    for (int r = 0; r < SPER; r++) {
        const u64* __restrict__ mp = (const u64*)(mS + r * 16);  // 7 packed pairs
        const float4 cv = *(const float4*)(cvp + r * 3 * 512);

        // temporal pair sums: tpX = sum_a (m_a, m_a) * (sin(a*div), cos(a*div))
        u64 t0, t1;
        {
            u64 m0 = mp[0];
            F2MUL(t0, m0, Tp0[0]);
            F2MUL(t1, m0, Tp1[0]);
        }
#pragma unroll
        for (int a = 1; a <= 6; a++) {
            u64 ma = mp[a];
            F2FMA(t0, ma, Tp0[a], t0);
            F2FMA(t1, ma, Tp1[a], t1);
        }
        float ts0, tc0, ts1, tc1;
        F2UNPACK(ts0, tc0, t0);
        F2UNPACK(ts1, tc1, t1);

        float4 res;
        res.x = cv.x + ps0 + ts0;
        res.y = cv.y + pc0 + tc0;
        res.z = cv.z + ps1 + ts1;
        res.w = cv.w + pc1 + tc1;
        *(float4*)outp = res;

        // rotate pe by div for next row
        float ns0 = ps0 * gc0 + pc0 * gs0;
        float nc0 = pc0 * gc0 - ps0 * gs0;
        float ns1 = ps1 * gc1 + pc1 * gs1;
        float nc1 = pc1 * gc1 - ps1 * gs1;
        ps0 = ns0; pc0 = nc0; ps1 = ns1; pc1 = nc1;

        outp += D;
    }
}

// ---------------- launch ----------------
extern "C" void kernel_launch(void* const* d_in, const int* in_sizes, int n_in,
                              void* d_out, int out_size)
{
    const float* x     = nullptr;
    const float* kern  = nullptr;
    const int*   xmark = nullptr;
    for (int i = 0; i < n_in; i++) {
        if      (in_sizes[i] == SEQ * CIN)        x     = (const float*)d_in[i];
        else if (in_sizes[i] == NUMK * KH * KW)   kern  = (const float*)d_in[i];
        else if (in_sizes[i] == SEQ * 4)          xmark = (const int*)d_in[i];
    }

    cudaFuncSetAttribute(embed_kernel,
                         cudaFuncAttributeMaxDynamicSharedMemorySize, SMEM_BYTES);

    embed_kernel<<<SEQ / SPER, NT, SMEM_BYTES>>>(x, kern, xmark, (float*)d_out);
}

// round 11
// speedup vs baseline: 1.3904x; 1.0217x over previous
#include <cuda_runtime.h>

#define SEQ   4096
#define CIN   7
#define NUMK  74
#define KH    8
#define KW    3
#define D     1536
#define HALFD 768
#define TLEN  (SEQ * KW)   // 12288
#define SPER  8            // s-rows per block
#define NH    (3 * SPER)   // 24 conv h-values per block
#define NT    384          // threads per block

// ---- packed f32x2 helpers (sm_100a) ----
typedef unsigned long long u64;
#define F2PACK(d, lo, hi)   asm("mov.b64 %0, {%1, %2};"      : "=l"(d) : "f"(lo), "f"(hi))
#define F2UNPACK(lo, hi, s) asm("mov.b64 {%0, %1}, %2;"      : "=f"(lo), "=f"(hi) : "l"(s))
#define F2MUL(d, a, b)      asm("mul.rn.f32x2 %0, %1, %2;"   : "=l"(d) : "l"(a), "l"(b))
#define F2FMA(d, a, b, c)   asm("fma.rn.f32x2 %0, %1, %2, %3;" : "=l"(d) : "l"(a), "l"(b), "l"(c))

// dynamic smem layout (floats):
//   convS [NH][512]   : 12288 @ 0
//   wcsS  [KH][76]    : 608   @ 12288
//   sxA   [CIN][32]   : 224   @ 12896   (window v[i])
//   sxB   [CIN][32]   : 224   @ 13120   (window v[i+1], staggered copy)
//   mS    [SPER][16]  : 128   @ 13344   (duplicated multiplicity pairs)
#define SM_CONV   0
#define SM_WCS    12288
#define SM_SXA    (SM_WCS + 608)
#define SM_SXB    (SM_SXA + 224)
#define SM_M      (SM_SXB + 224)
#define SMEM_BYTES ((SM_M + SPER * 16) * 4)

// packed-pair conv for one column: h in [hr, hr+2*nsteps), results to convS[h][g]
// dual staggered window copies make every (v_j, v_{j+1}) pair one aligned LDS.64
__device__ __forceinline__ void conv_col(
    const float* __restrict__ sxa,    // copyA: v[0..30]
    const float* __restrict__ sxb,    // copyB: v[1..30] at index i-1
    const float* __restrict__ wcsS,   // [k][76]
    int o, int g, int hr, int nsteps, // hr even
    float* __restrict__ convS)
{
    u64 wp[8];
#pragma unroll
    for (int k = 0; k < 8; k++) {
        float w = wcsS[k * 76 + o];
        F2PACK(wp[k], w, w);
    }
    // ring: P[j] = (v[hr+j], v[hr+j+1]);  even j from copyA, odd j from copyB
    u64 P[8];
#pragma unroll
    for (int j = 0; j < 8; j++) {
        P[j] = (j & 1) ? *(const u64*)(sxb + hr + j - 1)
                       : *(const u64*)(sxa + hr + j);
    }

#pragma unroll
    for (int t = 0; t < nsteps; t++) {
        const int h = hr + 2 * t;
        u64 acc;
        F2MUL(acc, wp[0], P[(2 * t) & 7]);
#pragma unroll
        for (int k = 1; k < 8; k++)
            F2FMA(acc, wp[k], P[(2 * t + k) & 7], acc);
        float lo, hi;
        F2UNPACK(lo, hi, acc);
        convS[h * 512 + g]       = lo;
        convS[(h + 1) * 512 + g] = hi;
        if (t < nsteps - 1) {
            P[(2 * t) & 7]     = *(const u64*)(sxa + hr + 2 * t + 8); // pair @ even 2t+8
            P[(2 * t + 1) & 7] = *(const u64*)(sxb + hr + 2 * t + 8); // pair @ odd  2t+9
        }
    }
}

// ---------------- single kernel: conv to smem, then tables-by-rotation ----------------
__global__ __launch_bounds__(NT, 3) void embed_kernel(
    const float* __restrict__ x,       // (4096, 7)
    const float* __restrict__ kern,    // (74, 8, 3)
    const int*   __restrict__ xm,      // (4096, 4)
    float*       __restrict__ out)     // (4096, 1536)
{
    extern __shared__ float smem[];
    float* __restrict__ convS = smem + SM_CONV;
    float* __restrict__ wcsS  = smem + SM_WCS;
    float* __restrict__ sxA   = smem + SM_SXA;
    float* __restrict__ sxB   = smem + SM_SXB;
    float* __restrict__ mS    = smem + SM_M;

    const int s0  = blockIdx.x * SPER;
    const int tid = threadIdx.x;

    // ---- stage weights: wc[o][k] = kern[o*24 + k*3 + 1]
    for (int e = tid; e < NUMK * KH; e += NT) {
        int o = e / KH, k = e - o * KH;
        wcsS[k * 76 + o] = kern[o * (KH * KW) + k * KW + 1];
    }
    // ---- stage x window (dual staggered copies): i in [0,31), t = 3*s0 - 4 + i
    if (tid < CIN * 31) {
        int c = tid / 31, i = tid - c * 31;
        int t = 3 * s0 - 4 + i;
        float v = 0.0f;
        if (t >= 0 && t < TLEN) {
            int row = t / 3 + t % 3;
            if (row > SEQ - 1) row = SEQ - 1;
            v = x[row * CIN + c];
        }
        sxA[c * 32 + i] = v;
        if (i > 0) sxB[c * 32 + i - 1] = v;
    }
    // ---- stage duplicated temporal multiplicity pairs:
    //      mS[r][2a, 2a+1] = (a==0 ? 0 : m, m) where m = #{k : xm[s0+r][k]==a}
    if (tid >= 320 && tid < 320 + SPER * 7) {
        int e = tid - 320;
        int r = e / 7, a = e - r * 7;
        const int* xr = xm + (s0 + r) * 4;
        float m = (float)((xr[0] == a) + (xr[1] == a) + (xr[2] == a) + (xr[3] == a));
        mS[r * 16 + 2 * a]     = (a == 0) ? 0.0f : m;
        mS[r * 16 + 2 * a + 1] = m;
    }
    __syncthreads();

    // =========== Phase 1 (balanced): full column g = tid; plus an 8-h chunk of cols 384..511 ==========
    {
        const int g = tid;                       // 0..383 -> c <= 5, never 511
        const int c = g / 73, o = g - c * 73;
        conv_col(sxA + c * 32, sxB + c * 32, wcsS, o, g, 0, NH / 2, convS);
    }
    {
        const int g  = 384 + (tid & 127);        // 384..511
        const int hr = (tid >> 7) * 8;           // 0, 8, 16
        int c, o;
        if (g == 511) { c = 0; o = NUMK - 1; }
        else          { c = g / 73; o = g - c * 73; }
        conv_col(sxA + c * 32, sxB + c * 32, wcsS, o, g, hr, 4, convS);
    }
    __syncthreads();

    // =========== Phase 2: one float4 column per thread; pe + temporal by rotation ==========
    const int lane = tid & 127;          // 0..127
    const int jj   = tid >> 7;           // 0..2
    const int g0   = 4 * lane;
    const int f    = jj * 512 + g0;      // even; dims f..f+3 = pairs (i0, i0+1)

    const float cexp = (float)(-9.210340371976184 / 1536.0); // -ln(10000)/d
    const float div0 = expf((float)(f) * cexp);              // div for i0 = f/2
    const float div1 = div0 * 0.988078993f;                  // * 10000^(-2/1536)

    // pe(s0) seed: large args -> accurate sincosf
    float ps0, pc0, ps1, pc1;
    sincosf((float)s0 * div0, &ps0, &pc0);
    sincosf((float)s0 * div1, &ps1, &pc1);
    // per-row rotation step: args <= 1 rad -> fast path
    float gs0, gc0, gs1, gc1;
    __sincosf(div0, &gs0, &gc0);
    __sincosf(div1, &gs1, &gc1);

    // packed temporal basis Tp[a] = (sin(a*div), cos(a*div)), a = 0..6
    u64 Tp0[7], Tp1[7];
    F2PACK(Tp0[0], 0.0f, 1.0f);
    F2PACK(Tp1[0], 0.0f, 1.0f);
    F2PACK(Tp0[1], gs0, gc0);
    F2PACK(Tp1[1], gs1, gc1);
    {
        float ts0 = gs0, tc0 = gc0, ts1 = gs1, tc1 = gc1;
#pragma unroll
        for (int a = 2; a <= 6; a++) {
            float ns0 = ts0 * gc0 + tc0 * gs0;
            float nc0 = tc0 * gc0 - ts0 * gs0;
            float ns1 = ts1 * gc1 + tc1 * gs1;
            float nc1 = tc1 * gc1 - ts1 * gs1;
            ts0 = ns0; tc0 = nc0; ts1 = ns1; tc1 = nc1;
            F2PACK(Tp0[a], ts0, tc0);
            F2PACK(Tp1[a], ts1, tc1);
        }
    }

    float* __restrict__ outp = out + (size_t)s0 * D + f;
    const float* __restrict__ cvp = convS + jj * 512 + g0;   // +1536 per row

#pragma unroll
    for (int r = 0; r < SPER; r++) {
        // 4x LDS.128 deliver the 7 multiplicity pairs (8th is pad)
        const ulonglong2* __restrict__ mp2 = (const ulonglong2*)(mS + r * 16);
        const ulonglong2 ma = mp2[0], mb = mp2[1], mc = mp2[2], md = mp2[3];
        const float4 cv = *(const float4*)(cvp + r * 3 * 512);

        u64 t0, t1;
        F2MUL(t0, ma.x, Tp0[0]);
        F2MUL(t1, ma.x, Tp1[0]);
        F2FMA(t0, ma.y, Tp0[1], t0);  F2FMA(t1, ma.y, Tp1[1], t1);
        F2FMA(t0, mb.x, Tp0[2], t0);  F2FMA(t1, mb.x, Tp1[2], t1);
        F2FMA(t0, mb.y, Tp0[3], t0);  F2FMA(t1, mb.y, Tp1[3], t1);
        F2FMA(t0, mc.x, Tp0[4], t0);  F2FMA(t1, mc.x, Tp1[4], t1);
        F2FMA(t0, mc.y, Tp0[5], t0);  F2FMA(t1, mc.y, Tp1[5], t1);
        F2FMA(t0, md.x, Tp0[6], t0);  F2FMA(t1, md.x, Tp1[6], t1);

        float ts0, tc0, ts1, tc1;
        F2UNPACK(ts0, tc0, t0);
        F2UNPACK(ts1, tc1, t1);

        float4 res;
        res.x = cv.x + ps0 + ts0;
        res.y = cv.y + pc0 + tc0;
        res.z = cv.z + ps1 + ts1;
        res.w = cv.w + pc1 + tc1;
        *(float4*)(outp) = res;

        // rotate pe by div for next row
        float ns0 = ps0 * gc0 + pc0 * gs0;
        float nc0 = pc0 * gc0 - ps0 * gs0;
        float ns1 = ps1 * gc1 + pc1 * gs1;
        float nc1 = pc1 * gc1 - ps1 * gs1;
        ps0 = ns0; pc0 = nc0; ps1 = ns1; pc1 = nc1;

        outp += D;
    }
}

// ---------------- launch ----------------
extern "C" void kernel_launch(void* const* d_in, const int* in_sizes, int n_in,
                              void* d_out, int out_size)
{
    const float* x     = nullptr;
    const float* kern  = nullptr;
    const int*   xmark = nullptr;
    for (int i = 0; i < n_in; i++) {
        if      (in_sizes[i] == SEQ * CIN)        x     = (const float*)d_in[i];
        else if (in_sizes[i] == NUMK * KH * KW)   kern  = (const float*)d_in[i];
        else if (in_sizes[i] == SEQ * 4)          xmark = (const int*)d_in[i];
    }

    cudaFuncSetAttribute(embed_kernel,
                         cudaFuncAttributeMaxDynamicSharedMemorySize, SMEM_BYTES);

    embed_kernel<<<SEQ / SPER, NT, SMEM_BYTES>>>(x, kern, xmark, (float*)d_out);
}

// round 12
// speedup vs baseline: 1.4571x; 1.0480x over previous
#include <cuda_runtime.h>

#define SEQ   4096
#define CIN   7
#define NUMK  74
#define KH    8
#define KW    3
#define D     1536
#define TLEN  (SEQ * KW)   // 12288
#define SPER  10           // s-rows per block (grid 410 <= 444 resident slots: single wave)
#define NH    (3 * SPER)   // 30 conv h-values per block
#define NT    384          // threads per block
#define WLEN  (3 * SPER + 7)  // 37 window values per channel
#define WPAD  40

// ---- packed f32x2 helpers (sm_100a) ----
typedef unsigned long long u64;
#define F2PACK(d, lo, hi)   asm("mov.b64 %0, {%1, %2};"      : "=l"(d) : "f"(lo), "f"(hi))
#define F2UNPACK(lo, hi, s) asm("mov.b64 {%0, %1}, %2;"      : "=f"(lo), "=f"(hi) : "l"(s))
#define F2MUL(d, a, b)      asm("mul.rn.f32x2 %0, %1, %2;"   : "=l"(d) : "l"(a), "l"(b))
#define F2FMA(d, a, b, c)   asm("fma.rn.f32x2 %0, %1, %2, %3;" : "=l"(d) : "l"(a), "l"(b), "l"(c))

// dynamic smem layout (floats):
#define SM_CONV   0                              // [NH][512] = 15360
#define SM_WCS    (SM_CONV + NH * 512)           // [KH][76]  = 608
#define SM_SXA    (SM_WCS + KH * 76)             // [CIN][40] = 280
#define SM_SXB    (SM_SXA + CIN * WPAD)          // [CIN][40] = 280
#define SM_M      (SM_SXB + CIN * WPAD)          // [SPER][16]= 160
#define SMEM_BYTES ((SM_M + SPER * 16) * 4)

// packed-pair conv for one column: h in [hr, hr+2*nsteps), results to convS[h][g]
// dual staggered window copies make every (v_j, v_{j+1}) pair one aligned LDS.64
__device__ __forceinline__ void conv_col(
    const float* __restrict__ sxa,    // copyA: v[i]
    const float* __restrict__ sxb,    // copyB: v[i+1] at index i
    const float* __restrict__ wcsS,   // [k][76]
    int o, int g, int hr, int nsteps, // hr even
    float* __restrict__ convS)
{
    u64 wp[8];
#pragma unroll
    for (int k = 0; k < 8; k++) {
        float w = wcsS[k * 76 + o];
        F2PACK(wp[k], w, w);
    }
    // ring: P[j] = (v[hr+j], v[hr+j+1]);  even j from copyA, odd j from copyB
    u64 P[8];
#pragma unroll
    for (int j = 0; j < 8; j++) {
        P[j] = (j & 1) ? *(const u64*)(sxb + hr + j - 1)
                       : *(const u64*)(sxa + hr + j);
    }

#pragma unroll
    for (int t = 0; t < nsteps; t++) {
        const int h = hr + 2 * t;
        u64 acc;
        F2MUL(acc, wp[0], P[(2 * t) & 7]);
#pragma unroll
        for (int k = 1; k < 8; k++)
            F2FMA(acc, wp[k], P[(2 * t + k) & 7], acc);
        float lo, hi;
        F2UNPACK(lo, hi, acc);
        convS[h * 512 + g]       = lo;
        convS[(h + 1) * 512 + g] = hi;
        if (t < nsteps - 1) {
            P[(2 * t) & 7]     = *(const u64*)(sxa + hr + 2 * t + 8);
            P[(2 * t + 1) & 7] = *(const u64*)(sxb + hr + 2 * t + 8);
        }
    }
}

// ---------------- single kernel: conv to smem, then tables-by-rotation ----------------
__global__ __launch_bounds__(NT, 3) void embed_kernel(
    const float* __restrict__ x,       // (4096, 7)
    const float* __restrict__ kern,    // (74, 8, 3)
    const int*   __restrict__ xm,      // (4096, 4)
    float*       __restrict__ out)     // (4096, 1536)
{
    extern __shared__ float smem[];
    float* __restrict__ convS = smem + SM_CONV;
    float* __restrict__ wcsS  = smem + SM_WCS;
    float* __restrict__ sxA   = smem + SM_SXA;
    float* __restrict__ sxB   = smem + SM_SXB;
    float* __restrict__ mS    = smem + SM_M;

    const int s0   = blockIdx.x * SPER;
    const int rmax = (SEQ - s0 < SPER) ? (SEQ - s0) : SPER;   // last block: 6
    const int tid  = threadIdx.x;

    // ---- stage weights: wc[o][k] = kern[o*24 + k*3 + 1]
    for (int e = tid; e < NUMK * KH; e += NT) {
        int o = e / KH, k = e - o * KH;
        wcsS[k * 76 + o] = kern[o * (KH * KW) + k * KW + 1];
    }
    // ---- stage x window (dual staggered copies): i in [0, WLEN), t = 3*s0 - 4 + i
    if (tid < CIN * WLEN) {
        int c = tid / WLEN, i = tid - c * WLEN;
        int t = 3 * s0 - 4 + i;
        float v = 0.0f;
        if (t >= 0 && t < TLEN) {
            int row = t / 3 + t % 3;
            if (row > SEQ - 1) row = SEQ - 1;
            v = x[row * CIN + c];
        }
        sxA[c * WPAD + i] = v;
        if (i > 0) sxB[c * WPAD + i - 1] = v;
    }
    // ---- stage duplicated temporal multiplicity pairs:
    //      mS[r][2a, 2a+1] = (a==0 ? 0 : m, m) where m = #{k : xm[s][k]==a}
    if (tid >= 288 && tid < 288 + SPER * 7) {
        int e = tid - 288;
        int r = e / 7, a = e - r * 7;
        int s = s0 + r; if (s > SEQ - 1) s = SEQ - 1;   // clamp (stores predicated off anyway)
        const int* xr = xm + s * 4;
        float m = (float)((xr[0] == a) + (xr[1] == a) + (xr[2] == a) + (xr[3] == a));
        mS[r * 16 + 2 * a]     = (a == 0) ? 0.0f : m;
        mS[r * 16 + 2 * a + 1] = m;
    }
    __syncthreads();

    // =========== Phase 1 (balanced): full column g = tid; plus a 10-h chunk of cols 384..511 ==========
    {
        const int g = tid;                       // 0..383 -> c <= 5, never 511
        const int c = g / 73, o = g - c * 73;
        conv_col(sxA + c * WPAD, sxB + c * WPAD, wcsS, o, g, 0, NH / 2, convS);
    }
    {
        const int g  = 384 + (tid & 127);        // 384..511
        const int hr = (tid >> 7) * SPER;        // 0, 10, 20 (even)
        int c, o;
        if (g == 511) { c = 0; o = NUMK - 1; }
        else          { c = g / 73; o = g - c * 73; }
        conv_col(sxA + c * WPAD, sxB + c * WPAD, wcsS, o, g, hr, SPER / 2, convS);
    }
    __syncthreads();

    // =========== Phase 2: one float4 column per thread; pe + temporal by rotation ==========
    const int lane = tid & 127;          // 0..127
    const int jj   = tid >> 7;           // 0..2
    const int g0   = 4 * lane;
    const int f    = jj * 512 + g0;      // even; dims f..f+3 = pairs (i0, i0+1)

    const float cexp = (float)(-9.210340371976184 / 1536.0); // -ln(10000)/d
    const float div0 = expf((float)(f) * cexp);
    const float div1 = div0 * 0.988078993f;                  // * 10000^(-2/1536)

    // pe(s0) seed: large args -> accurate sincosf
    float ps0, pc0, ps1, pc1;
    sincosf((float)s0 * div0, &ps0, &pc0);
    sincosf((float)s0 * div1, &ps1, &pc1);
    // per-row rotation step: args <= 1 rad -> fast path
    float gs0, gc0, gs1, gc1;
    __sincosf(div0, &gs0, &gc0);
    __sincosf(div1, &gs1, &gc1);

    // packed temporal basis Tp[a] = (sin(a*div), cos(a*div)), a = 1..6
    u64 Tp0[7], Tp1[7];
    F2PACK(Tp0[1], gs0, gc0);
    F2PACK(Tp1[1], gs1, gc1);
    {
        float ts0 = gs0, tc0 = gc0, ts1 = gs1, tc1 = gc1;
#pragma unroll
        for (int a = 2; a <= 6; a++) {
            float ns0 = ts0 * gc0 + tc0 * gs0;
            float nc0 = tc0 * gc0 - ts0 * gs0;
            float ns1 = ts1 * gc1 + tc1 * gs1;
            float nc1 = tc1 * gc1 - ts1 * gs1;
            ts0 = ns0; tc0 = nc0; ts1 = ns1; tc1 = nc1;
            F2PACK(Tp0[a], ts0, tc0);
            F2PACK(Tp1[a], ts1, tc1);
        }
    }

    float* __restrict__ outp = out + (size_t)s0 * D + f;
    const float* __restrict__ cvp = convS + jj * 512 + g0;   // +1536 per row

#pragma unroll
    for (int r = 0; r < SPER; r++) {
        const ulonglong2* __restrict__ mp2 = (const ulonglong2*)(mS + r * 16);
        const ulonglong2 ma = mp2[0], mb = mp2[1], mc = mp2[2], md = mp2[3];
        const float4 cv = *(const float4*)(cvp + r * 3 * 512);

        // t init: ma.x = (0, m0); multiplying by (sin0, cos0) = (0, 1) is identity
        u64 t0 = ma.x, t1 = ma.x;
        F2FMA(t0, ma.y, Tp0[1], t0);  F2FMA(t1, ma.y, Tp1[1], t1);
        F2FMA(t0, mb.x, Tp0[2], t0);  F2FMA(t1, mb.x, Tp1[2], t1);
        F2FMA(t0, mb.y, Tp0[3], t0);  F2FMA(t1, mb.y, Tp1[3], t1);
        F2FMA(t0, mc.x, Tp0[4], t0);  F2FMA(t1, mc.x, Tp1[4], t1);
        F2FMA(t0, mc.y, Tp0[5], t0);  F2FMA(t1, mc.y, Tp1[5], t1);
        F2FMA(t0, md.x, Tp0[6], t0);  F2FMA(t1, md.x, Tp1[6], t1);

        float ts0, tc0, ts1, tc1;
        F2UNPACK(ts0, tc0, t0);
        F2UNPACK(ts1, tc1, t1);

        float4 res;
        res.x = cv.x + ps0 + ts0;
        res.y = cv.y + pc0 + tc0;
        res.z = cv.z + ps1 + ts1;
        res.w = cv.w + pc1 + tc1;
        if (r < rmax)
            *(float4*)(outp) = res;

        // rotate pe by div for next row
        float ns0 = ps0 * gc0 + pc0 * gs0;
        float nc0 = pc0 * gc0 - ps0 * gs0;
        float ns1 = ps1 * gc1 + pc1 * gs1;
        float nc1 = pc1 * gc1 - ps1 * gs1;
        ps0 = ns0; pc0 = nc0; ps1 = ns1; pc1 = nc1;

        outp += D;
    }
}

// ---------------- launch ----------------
extern "C" void kernel_launch(void* const* d_in, const int* in_sizes, int n_in,
                              void* d_out, int out_size)
{
    const float* x     = nullptr;
    const float* kern  = nullptr;
    const int*   xmark = nullptr;
    for (int i = 0; i < n_in; i++) {
        if      (in_sizes[i] == SEQ * CIN)        x     = (const float*)d_in[i];
        else if (in_sizes[i] == NUMK * KH * KW)   kern  = (const float*)d_in[i];
        else if (in_sizes[i] == SEQ * 4)          xmark = (const int*)d_in[i];
    }

    cudaFuncSetAttribute(embed_kernel,
                         cudaFuncAttributeMaxDynamicSharedMemorySize, SMEM_BYTES);

    const int nblocks = (SEQ + SPER - 1) / SPER;   // 410
    embed_kernel<<<nblocks, NT, SMEM_BYTES>>>(x, kern, xmark, (float*)d_out);
}

// round 13
// speedup vs baseline: 1.4910x; 1.0233x over previous
#include <cuda_runtime.h>

#define SEQ   4096
#define CIN   7
#define NUMK  74
#define KH    8
#define KW    3
#define D     1536
#define TLEN  (SEQ * KW)   // 12288
#define NBLK  444          // one block per resident slot (148 SMs x 3): perfectly balanced
#define SPER  10           // max rows per block (blocks own 9 or 10 rows)
#define NH    (3 * SPER)   // 30 conv h-values per block (fixed; 9-row blocks waste 3)
#define NT    384          // threads per block
#define WLEN  (3 * SPER + 7)  // 37 window values per channel
#define WPAD  40

// ---- packed f32x2 helpers (sm_100a) ----
typedef unsigned long long u64;
#define F2PACK(d, lo, hi)   asm("mov.b64 %0, {%1, %2};"      : "=l"(d) : "f"(lo), "f"(hi))
#define F2UNPACK(lo, hi, s) asm("mov.b64 {%0, %1}, %2;"      : "=f"(lo), "=f"(hi) : "l"(s))
#define F2MUL(d, a, b)      asm("mul.rn.f32x2 %0, %1, %2;"   : "=l"(d) : "l"(a), "l"(b))
#define F2FMA(d, a, b, c)   asm("fma.rn.f32x2 %0, %1, %2, %3;" : "=l"(d) : "l"(a), "l"(b), "l"(c))

// dynamic smem layout (floats):
#define SM_CONV   0                              // [NH][512] = 15360
#define SM_WCS    (SM_CONV + NH * 512)           // [KH][76]  = 608
#define SM_SXA    (SM_WCS + KH * 76)             // [CIN][40] = 280
#define SM_SXB    (SM_SXA + CIN * WPAD)          // [CIN][40] = 280
#define SM_M      (SM_SXB + CIN * WPAD)          // [SPER][16]= 160
#define SMEM_BYTES ((SM_M + SPER * 16) * 4)

// packed-pair conv for one column: h in [hr, hr+2*nsteps), results to convS[h][g]
// dual staggered window copies make every (v_j, v_{j+1}) pair one aligned LDS.64
__device__ __forceinline__ void conv_col(
    const float* __restrict__ sxa,    // copyA: v[i]
    const float* __restrict__ sxb,    // copyB: v[i+1] at index i
    const float* __restrict__ wcsS,   // [k][76]
    int o, int g, int hr, int nsteps, // hr even
    float* __restrict__ convS)
{
    u64 wp[8];
#pragma unroll
    for (int k = 0; k < 8; k++) {
        float w = wcsS[k * 76 + o];
        F2PACK(wp[k], w, w);
    }
    // ring: P[j] = (v[hr+j], v[hr+j+1]);  even j from copyA, odd j from copyB
    u64 P[8];
#pragma unroll
    for (int j = 0; j < 8; j++) {
        P[j] = (j & 1) ? *(const u64*)(sxb + hr + j - 1)
                       : *(const u64*)(sxa + hr + j);
    }

#pragma unroll
    for (int t = 0; t < nsteps; t++) {
        const int h = hr + 2 * t;
        u64 acc;
        F2MUL(acc, wp[0], P[(2 * t) & 7]);
#pragma unroll
        for (int k = 1; k < 8; k++)
            F2FMA(acc, wp[k], P[(2 * t + k) & 7], acc);
        float lo, hi;
        F2UNPACK(lo, hi, acc);
        convS[h * 512 + g]       = lo;
        convS[(h + 1) * 512 + g] = hi;
        if (t < nsteps - 1) {
            P[(2 * t) & 7]     = *(const u64*)(sxa + hr + 2 * t + 8);
            P[(2 * t + 1) & 7] = *(const u64*)(sxb + hr + 2 * t + 8);
        }
    }
}

// ---------------- single kernel: conv to smem, then tables-by-rotation ----------------
__global__ __launch_bounds__(NT, 3) void embed_kernel(
    const float* __restrict__ x,       // (4096, 7)
    const float* __restrict__ kern,    // (74, 8, 3)
    const int*   __restrict__ xm,      // (4096, 4)
    float*       __restrict__ out)     // (4096, 1536)
{
    extern __shared__ float smem[];
    float* __restrict__ convS = smem + SM_CONV;
    float* __restrict__ wcsS  = smem + SM_WCS;
    float* __restrict__ sxA   = smem + SM_SXA;
    float* __restrict__ sxB   = smem + SM_SXB;
    float* __restrict__ mS    = smem + SM_M;

    // balanced partition: block b owns rows [b*SEQ/NBLK, (b+1)*SEQ/NBLK)  -> 9 or 10 rows
    const int b    = blockIdx.x;
    const int s0   = (b * SEQ) / NBLK;
    const int rmax = ((b + 1) * SEQ) / NBLK - s0;
    const int tid  = threadIdx.x;

    // ---- stage weights: wc[o][k] = kern[o*24 + k*3 + 1]
    for (int e = tid; e < NUMK * KH; e += NT) {
        int o = e / KH, k = e - o * KH;
        wcsS[k * 76 + o] = kern[o * (KH * KW) + k * KW + 1];
    }
    // ---- stage x window (dual staggered copies): i in [0, WLEN), t = 3*s0 - 4 + i
    if (tid < CIN * WLEN) {
        int c = tid / WLEN, i = tid - c * WLEN;
        int t = 3 * s0 - 4 + i;
        float v = 0.0f;
        if (t >= 0 && t < TLEN) {
            int row = t / 3 + t % 3;
            if (row > SEQ - 1) row = SEQ - 1;
            v = x[row * CIN + c];
        }
        sxA[c * WPAD + i] = v;
        if (i > 0) sxB[c * WPAD + i - 1] = v;
    }
    // ---- stage duplicated temporal multiplicity pairs:
    //      mS[r][2a, 2a+1] = (a==0 ? 0 : m, m) where m = #{k : xm[s][k]==a}
    if (tid >= 288 && tid < 288 + SPER * 7) {
        int e = tid - 288;
        int r = e / 7, a = e - r * 7;
        int s = s0 + r; if (s > SEQ - 1) s = SEQ - 1;   // clamp (stores predicated off anyway)
        const int* xr = xm + s * 4;
        float m = (float)((xr[0] == a) + (xr[1] == a) + (xr[2] == a) + (xr[3] == a));
        mS[r * 16 + 2 * a]     = (a == 0) ? 0.0f : m;
        mS[r * 16 + 2 * a + 1] = m;
    }
    __syncthreads();

    // =========== Phase 1 (balanced, fixed 30 h): full column g = tid; plus a 10-h chunk ==========
    {
        const int g = tid;                       // 0..383 -> c <= 5, never 511
        const int c = g / 73, o = g - c * 73;
        conv_col(sxA + c * WPAD, sxB + c * WPAD, wcsS, o, g, 0, NH / 2, convS);
    }
    {
        const int g  = 384 + (tid & 127);        // 384..511
        const int hr = (tid >> 7) * SPER;        // 0, 10, 20 (even)
        int c, o;
        if (g == 511) { c = 0; o = NUMK - 1; }
        else          { c = g / 73; o = g - c * 73; }
        conv_col(sxA + c * WPAD, sxB + c * WPAD, wcsS, o, g, hr, SPER / 2, convS);
    }
    __syncthreads();

    // =========== Phase 2: one float4 column per thread; pe + temporal by rotation ==========
    const int lane = tid & 127;          // 0..127
    const int jj   = tid >> 7;           // 0..2
    const int g0   = 4 * lane;
    const int f    = jj * 512 + g0;      // even; dims f..f+3 = pairs (i0, i0+1)

    const float cexp = (float)(-9.210340371976184 / 1536.0); // -ln(10000)/d
    const float div0 = expf((float)(f) * cexp);
    const float div1 = div0 * 0.988078993f;                  // * 10000^(-2/1536)

    // pe(s0) seed: large args -> accurate sincosf
    float ps0, pc0, ps1, pc1;
    sincosf((float)s0 * div0, &ps0, &pc0);
    sincosf((float)s0 * div1, &ps1, &pc1);
    // per-row rotation step: args <= 1 rad -> fast path
    float gs0, gc0, gs1, gc1;
    __sincosf(div0, &gs0, &gc0);
    __sincosf(div1, &gs1, &gc1);

    // packed temporal basis Tp[a] = (sin(a*div), cos(a*div)), a = 1..6
    u64 Tp0[7], Tp1[7];
    F2PACK(Tp0[1], gs0, gc0);
    F2PACK(Tp1[1], gs1, gc1);
    {
        float ts0 = gs0, tc0 = gc0, ts1 = gs1, tc1 = gc1;
#pragma unroll
        for (int a = 2; a <= 6; a++) {
            float ns0 = ts0 * gc0 + tc0 * gs0;
            float nc0 = tc0 * gc0 - ts0 * gs0;
            float ns1 = ts1 * gc1 + tc1 * gs1;
            float nc1 = tc1 * gc1 - ts1 * gs1;
            ts0 = ns0; tc0 = nc0; ts1 = ns1; tc1 = nc1;
            F2PACK(Tp0[a], ts0, tc0);
            F2PACK(Tp1[a], ts1, tc1);
        }
    }

    float* __restrict__ outp = out + (size_t)s0 * D + f;
    const float* __restrict__ cvp = convS + jj * 512 + g0;   // +1536 per row

#pragma unroll
    for (int r = 0; r < SPER; r++) {
        const ulonglong2* __restrict__ mp2 = (const ulonglong2*)(mS + r * 16);
        const ulonglong2 ma = mp2[0], mb = mp2[1], mc = mp2[2], md = mp2[3];
        const float4 cv = *(const float4*)(cvp + r * 3 * 512);

        // t init: ma.x = (0, m0); multiplying by (sin0, cos0) = (0, 1) is identity
        u64 t0 = ma.x, t1 = ma.x;
        F2FMA(t0, ma.y, Tp0[1], t0);  F2FMA(t1, ma.y, Tp1[1], t1);
        F2FMA(t0, mb.x, Tp0[2], t0);  F2FMA(t1, mb.x, Tp1[2], t1);
        F2FMA(t0, mb.y, Tp0[3], t0);  F2FMA(t1, mb.y, Tp1[3], t1);
        F2FMA(t0, mc.x, Tp0[4], t0);  F2FMA(t1, mc.x, Tp1[4], t1);
        F2FMA(t0, mc.y, Tp0[5], t0);  F2FMA(t1, mc.y, Tp1[5], t1);
        F2FMA(t0, md.x, Tp0[6], t0);  F2FMA(t1, md.x, Tp1[6], t1);

        float ts0, tc0, ts1, tc1;
        F2UNPACK(ts0, tc0, t0);
        F2UNPACK(ts1, tc1, t1);

        float4 res;
        res.x = cv.x + ps0 + ts0;
        res.y = cv.y + pc0 + tc0;
        res.z = cv.z + ps1 + ts1;
        res.w = cv.w + pc1 + tc1;
        if (r < rmax)
            *(float4*)(outp) = res;

        // rotate pe by div for next row
        float ns0 = ps0 * gc0 + pc0 * gs0;
        float nc0 = pc0 * gc0 - ps0 * gs0;
        float ns1 = ps1 * gc1 + pc1 * gs1;
        float nc1 = pc1 * gc1 - ps1 * gs1;
        ps0 = ns0; pc0 = nc0; ps1 = ns1; pc1 = nc1;

        outp += D;
    }
}

// ---------------- launch ----------------
extern "C" void kernel_launch(void* const* d_in, const int* in_sizes, int n_in,
                              void* d_out, int out_size)
{
    const float* x     = nullptr;
    const float* kern  = nullptr;
    const int*   xmark = nullptr;
    for (int i = 0; i < n_in; i++) {
        if      (in_sizes[i] == SEQ * CIN)        x     = (const float*)d_in[i];
        else if (in_sizes[i] == NUMK * KH * KW)   kern  = (const float*)d_in[i];
        else if (in_sizes[i] == SEQ * 4)          xmark = (const int*)d_in[i];
    }

    cudaFuncSetAttribute(embed_kernel,
                         cudaFuncAttributeMaxDynamicSharedMemorySize, SMEM_BYTES);

    embed_kernel<<<NBLK, NT, SMEM_BYTES>>>(x, kern, xmark, (float*)d_out);
}